// round 2
// baseline (speedup 1.0000x reference)
#include <cuda_runtime.h>
#include <cstdint>

// Problem constants
#define BB   8
#define TT   2048
#define DD   1024
#define HH   4
#define HSZ  256
#define KC   4
#define UU   1365
#define UPAD 1368          // U padded to multiple of 8 for aligned float4 GEMM loads
#define BT   (BB*TT)       // 16384

// ---------------- scratch (static device globals; allocation-free rule) ----------
__device__ float g_xn    [BT * DD];            //  64 MB  layernormed x
__device__ float g_ifin  [BT * DD];            //  64 MB  swish(conv(xn))
__device__ float g_lin_if[(size_t)BT * 2048];  // 128 MB  weight_if @ ifin
__device__ float g_lin_zo[(size_t)BT * 2048];  // 128 MB  weight_zo @ xn
__device__ float g_zn    [BT * DD];            //  64 MB  post-scan groupnormed h
__device__ float g_up    [(size_t)BT * 2730];  // 179 MB  up projection (raw)
__device__ float g_act   [(size_t)BT * UPAD];  //  90 MB  gelu(u1)*u2 (zero-padded)
__device__ float g_whht  [HH * HSZ * DD];      //   4 MB  weight_hh transposed: [h][k][row]
__device__ float g_dwpad [DD * UPAD];          // 5.6 MB  down_w zero-padded to K=1368

// ---------------- LayerNorm over D=1024 per (b,t) row --------------------------
__global__ void ln_kernel(const float* __restrict__ x,
                          const float* __restrict__ lnw,
                          const float* __restrict__ lnb,
                          float* __restrict__ xn) {
    int row = blockIdx.x;            // 0..BT-1
    int tid = threadIdx.x;           // 256 threads, 4 elems each
    const float4* xr = (const float4*)(x + (size_t)row * DD);
    float4 v = xr[tid];
    float s1 = v.x + v.y + v.z + v.w;
    float s2 = v.x*v.x + v.y*v.y + v.z*v.z + v.w*v.w;
    for (int o = 16; o; o >>= 1) {
        s1 += __shfl_xor_sync(0xffffffffu, s1, o);
        s2 += __shfl_xor_sync(0xffffffffu, s2, o);
    }
    __shared__ float rs1[8], rs2[8];
    if ((tid & 31) == 0) { rs1[tid >> 5] = s1; rs2[tid >> 5] = s2; }
    __syncthreads();
    float t1 = 0.f, t2 = 0.f;
#pragma unroll
    for (int w = 0; w < 8; w++) { t1 += rs1[w]; t2 += rs2[w]; }
    float mean = t1 * (1.0f / DD);
    float var  = t2 * (1.0f / DD) - mean * mean;
    float rstd = rsqrtf(var + 1e-5f);
    float4 wv = ((const float4*)lnw)[tid];
    float4 bv = ((const float4*)lnb)[tid];
    float4 o4;
    o4.x = (v.x - mean) * rstd * wv.x + bv.x;
    o4.y = (v.y - mean) * rstd * wv.y + bv.y;
    o4.z = (v.z - mean) * rstd * wv.z + bv.z;
    o4.w = (v.w - mean) * rstd * wv.w + bv.w;
    ((float4*)(xn + (size_t)row * DD))[tid] = o4;
}

// ---------------- causal depthwise conv (K=4 taps over t) + swish --------------
__global__ void conv_kernel(const float* __restrict__ xn,
                            const float* __restrict__ convw,   // (D,4) row-major
                            const float* __restrict__ convb,
                            float* __restrict__ ifin) {
    int idx = blockIdx.x * blockDim.x + threadIdx.x;   // over BT*DD
    if (idx >= BT * DD) return;
    int c  = idx & (DD - 1);
    int bt = idx >> 10;
    int t  = bt & (TT - 1);
    int b  = bt >> 11;
    float4 w4 = ((const float4*)convw)[c];
    const float wk[4] = { w4.x, w4.y, w4.z, w4.w };
    float acc = convb[c];
#pragma unroll
    for (int k = 0; k < KC; k++) {
        int tt = t - 3 + k;
        float xv = (tt >= 0) ? xn[((size_t)(b * TT + tt) << 10) + c] : 0.f;
        acc = fmaf(wk[k], xv, acc);
    }
    ifin[idx] = acc / (1.f + expf(-acc));   // swish = x*sigmoid(x)
}

// ---------------- one-time weight prep kernels ---------------------------------
// whh_t[(h*256 + k)*1024 + r] = whh[(h*1024 + r)*256 + k]
__global__ void twhh_kernel(const float* __restrict__ whh, float* __restrict__ whht) {
    int idx = blockIdx.x * blockDim.x + threadIdx.x;   // H*256*1024 = 1048576
    if (idx >= HH * HSZ * DD) return;
    int h   = idx >> 18;
    int rem = idx & 262143;
    int k   = rem >> 10;
    int r   = rem & 1023;
    whht[idx] = whh[((size_t)(h * DD + r)) * HSZ + k];
}

__global__ void pad_dw_kernel(const float* __restrict__ dw, float* __restrict__ out) {
    int idx = blockIdx.x * blockDim.x + threadIdx.x;   // DD*UPAD
    if (idx >= DD * UPAD) return;
    int r = idx / UPAD, k = idx - r * UPAD;
    out[idx] = (k < UU) ? dw[(size_t)r * UU + k] : 0.f;
}

// ---------------- recurrent scan: 32 CTAs = (b,h) lanes ------------------------
__global__ void __launch_bounds__(256) scan_kernel(
        const float* __restrict__ lin_if,   // [BT][2048]
        const float* __restrict__ lin_zo,   // [BT][2048]
        const float* __restrict__ whht,     // [H][256][1024]
        const float* __restrict__ bias,     // [H][1024]
        const float* __restrict__ gn_w,
        const float* __restrict__ gn_b,
        float* __restrict__ zn)             // [BT][1024]
{
    int b   = blockIdx.x >> 2;
    int h   = blockIdx.x & 3;
    int tid = threadIdx.x;                  // 256; thread = HS index s / 4 matvec rows

    __shared__ float h_sm[HSZ];
    __shared__ float acc_sm[4 * HSZ];
    __shared__ float red_sm[16];

    h_sm[tid] = 0.f;
    float c_s = 0.f, n_s = 0.f, m_s = 0.f;

    const float* wt_base = whht + (size_t)h * HSZ * DD + 4 * tid;  // + k*1024
    float b_i = bias[h * DD + tid];
    float b_f = bias[h * DD + 256 + tid];
    float b_z = bias[h * DD + 512 + tid];
    float b_o = bias[h * DD + 768 + tid];
    float gw  = gn_w[h * HSZ + tid];
    float gb  = gn_b[h * HSZ + tid];
    __syncthreads();

    for (int t = 0; t < TT; t++) {
        // matvec: rows 4*tid..4*tid+3 of weight_hh[h] (k-major, coalesced LDG.128)
        float4 acc4 = make_float4(0.f, 0.f, 0.f, 0.f);
        const float* wp = wt_base;
#pragma unroll 8
        for (int k = 0; k < HSZ; ++k) {
            float hk = h_sm[k];
            float4 w = *(const float4*)wp;
            acc4.x = fmaf(w.x, hk, acc4.x);
            acc4.y = fmaf(w.y, hk, acc4.y);
            acc4.z = fmaf(w.z, hk, acc4.z);
            acc4.w = fmaf(w.w, hk, acc4.w);
            wp += DD;
        }
        *(float4*)(acc_sm + 4 * tid) = acc4;
        __syncthreads();

        // gates for HS index s = tid
        size_t row = (size_t)(b * TT + t);
        const float* lif = lin_if + row * 2048 + h * 512;
        const float* lzo = lin_zo + row * 2048 + h * 512;
        float iv = lif[tid]       + b_i + acc_sm[tid];
        float fv = lif[256 + tid] + b_f + acc_sm[256 + tid];
        float zv = lzo[tid]       + b_z + acc_sm[512 + tid];
        float ov = lzo[256 + tid] + b_o + acc_sm[768 + tid];
        float zg = tanhf(zv);
        float og = 1.f / (1.f + expf(-ov));
        float mn = fmaxf(fv + m_s, iv);
        float ie = expf(iv - mn);
        float fe = expf(fv + m_s - mn);
        c_s = fe * c_s + ie * zg;
        n_s = fe * n_s + ie;
        m_s = mn;
        float hval = og * (c_s / n_s);

        // groupnorm over the head's 256 values
        float s1 = hval, s2 = hval * hval;
        for (int o = 16; o; o >>= 1) {
            s1 += __shfl_xor_sync(0xffffffffu, s1, o);
            s2 += __shfl_xor_sync(0xffffffffu, s2, o);
        }
        if ((tid & 31) == 0) { red_sm[tid >> 5] = s1; red_sm[8 + (tid >> 5)] = s2; }
        __syncthreads();
        float t1 = 0.f, t2 = 0.f;
#pragma unroll
        for (int w = 0; w < 8; w++) { t1 += red_sm[w]; t2 += red_sm[8 + w]; }
        float mean = t1 * (1.0f / HSZ);
        float var  = t2 * (1.0f / HSZ) - mean * mean;
        float znv  = (hval - mean) * rsqrtf(var + 1e-5f) * gw + gb;
        zn[row * DD + h * HSZ + tid] = znv;

        h_sm[tid] = hval;          // raw h_new carries to next step
        __syncthreads();
    }
}

// ---------------- fp32 GEMM:  C[m][n] = sum_k A[m][k]*W[n][k]  (both K-major) ---
// MODE 0: plain store   MODE 1: +bias[n]   MODE 2: +bias[n] + resid[m*ldc+n]
template <int MODE>
__global__ void __launch_bounds__(256) gemm_tn(
        const float* __restrict__ A, const float* __restrict__ W,
        float* __restrict__ C,
        int M, int N, int K, int lda, int ldw, int ldc,
        const float* __restrict__ bias, const float* __restrict__ resid)
{
    __shared__ float As[8][128];
    __shared__ float Ws[8][128];
    int bm = blockIdx.x * 128;
    int bn = blockIdx.y * 128;
    int tid = threadIdx.x;
    int lr = tid >> 1;          // loader row 0..127
    int lc = (tid & 1) * 4;     // loader col 0 or 4
    int tx = tid & 15;          // 16x16 threads, 8x8 micro-tile
    int ty = tid >> 4;

    const float* Aptr = A + (size_t)(bm + lr) * lda + lc;
    int wrow = bn + lr;
    bool wvalid = (wrow < N);
    const float* Wptr = W + (size_t)(wvalid ? wrow : 0) * ldw + lc;

    float acc[8][8];
#pragma unroll
    for (int i = 0; i < 8; i++)
#pragma unroll
        for (int j = 0; j < 8; j++) acc[i][j] = 0.f;

    for (int k0 = 0; k0 < K; k0 += 8) {
        float4 av = *(const float4*)(Aptr + k0);
        float4 wv = wvalid ? *(const float4*)(Wptr + k0)
                           : make_float4(0.f, 0.f, 0.f, 0.f);
        As[lc + 0][lr] = av.x; As[lc + 1][lr] = av.y;
        As[lc + 2][lr] = av.z; As[lc + 3][lr] = av.w;
        Ws[lc + 0][lr] = wv.x; Ws[lc + 1][lr] = wv.y;
        Ws[lc + 2][lr] = wv.z; Ws[lc + 3][lr] = wv.w;
        __syncthreads();
#pragma unroll
        for (int kk = 0; kk < 8; kk++) {
            float ra[8], rb[8];
#pragma unroll
            for (int i = 0; i < 8; i++) ra[i] = As[kk][ty * 8 + i];
#pragma unroll
            for (int j = 0; j < 8; j++) rb[j] = Ws[kk][tx * 8 + j];
#pragma unroll
            for (int i = 0; i < 8; i++)
#pragma unroll
                for (int j = 0; j < 8; j++)
                    acc[i][j] = fmaf(ra[i], rb[j], acc[i][j]);
        }
        __syncthreads();
    }

#pragma unroll
    for (int i = 0; i < 8; i++) {
        int m = bm + ty * 8 + i;
#pragma unroll
        for (int j = 0; j < 8; j++) {
            int n = bn + tx * 8 + j;
            if (n < N) {
                float v = acc[i][j];
                if (MODE >= 1) v += bias[n];
                if (MODE == 2) v += resid[(size_t)m * ldc + n];
                C[(size_t)m * ldc + n] = v;
            }
        }
    }
}

// ---------------- gelu(u1)*u2 with zero-padding to UPAD ------------------------
__global__ void act_kernel(const float* __restrict__ up, float* __restrict__ act) {
    int idx = blockIdx.x * blockDim.x + threadIdx.x;   // over BT*UPAD
    if (idx >= BT * UPAD) return;
    int row = idx / UPAD, j = idx - row * UPAD;
    float v = 0.f;
    if (j < UU) {
        float u1 = up[(size_t)row * 2730 + j];
        float u2 = up[(size_t)row * 2730 + UU + j];
        // jax.nn.gelu default = tanh approximation
        float g = 0.5f * u1 * (1.f + tanhf(0.7978845608028654f *
                                           (u1 + 0.044715f * u1 * u1 * u1)));
        v = g * u2;
    }
    act[idx] = v;
}

// ---------------- launch ---------------------------------------------------------
extern "C" void kernel_launch(void* const* d_in, const int* in_sizes, int n_in,
                              void* d_out, int out_size) {
    const float* x      = (const float*)d_in[0];
    const float* ln_w   = (const float*)d_in[1];
    const float* ln_b   = (const float*)d_in[2];
    const float* conv_w = (const float*)d_in[3];
    const float* conv_b = (const float*)d_in[4];
    const float* w_if   = (const float*)d_in[5];
    const float* w_zo   = (const float*)d_in[6];
    const float* w_hh   = (const float*)d_in[7];
    const float* bias   = (const float*)d_in[8];
    const float* gn_w   = (const float*)d_in[9];
    const float* gn_b   = (const float*)d_in[10];
    const float* up_w   = (const float*)d_in[11];
    const float* up_b   = (const float*)d_in[12];
    const float* down_w = (const float*)d_in[13];
    const float* down_b = (const float*)d_in[14];
    float* out = (float*)d_out;

    static float *p_xn = nullptr, *p_ifin, *p_lif, *p_lzo, *p_zn, *p_up, *p_act,
                 *p_whht, *p_dwpad;
    if (!p_xn) {
        cudaGetSymbolAddress((void**)&p_xn,    g_xn);
        cudaGetSymbolAddress((void**)&p_ifin,  g_ifin);
        cudaGetSymbolAddress((void**)&p_lif,   g_lin_if);
        cudaGetSymbolAddress((void**)&p_lzo,   g_lin_zo);
        cudaGetSymbolAddress((void**)&p_zn,    g_zn);
        cudaGetSymbolAddress((void**)&p_up,    g_up);
        cudaGetSymbolAddress((void**)&p_act,   g_act);
        cudaGetSymbolAddress((void**)&p_whht,  g_whht);
        cudaGetSymbolAddress((void**)&p_dwpad, g_dwpad);
    }

    // weight prep (cheap; re-run every call for determinism under graph replay)
    twhh_kernel  <<<(HH * HSZ * DD + 255) / 256, 256>>>(w_hh, p_whht);
    pad_dw_kernel<<<(DD * UPAD + 255) / 256, 256>>>(down_w, p_dwpad);

    // Phase A: LN -> conv+swish -> two big GEMMs (parallel over all B*T)
    ln_kernel  <<<BT, 256>>>(x, ln_w, ln_b, p_xn);
    conv_kernel<<<(BT * DD + 255) / 256, 256>>>(p_xn, conv_w, conv_b, p_ifin);
    gemm_tn<0><<<dim3(BT / 128, 2048 / 128), 256>>>(
        p_ifin, w_if, p_lif, BT, 2048, 1024, 1024, 1024, 2048, nullptr, nullptr);
    gemm_tn<0><<<dim3(BT / 128, 2048 / 128), 256>>>(
        p_xn, w_zo, p_lzo, BT, 2048, 1024, 1024, 1024, 2048, nullptr, nullptr);

    // Phase B: sequential sLSTM scan, 32 independent (batch, head) lanes
    scan_kernel<<<32, 256>>>(p_lif, p_lzo, p_whht, bias, gn_w, gn_b, p_zn);

    // Phase C: MLP as batched GEMMs + fused residual
    gemm_tn<1><<<dim3(BT / 128, (2730 + 127) / 128), 256>>>(
        p_zn, up_w, p_up, BT, 2730, 1024, 1024, 1024, 2730, up_b, nullptr);
    act_kernel<<<(BT * UPAD + 255) / 256, 256>>>(p_up, p_act);
    gemm_tn<2><<<dim3(BT / 128, 1024 / 128), 256>>>(
        p_act, p_dwpad, out, BT, 1024, UPAD, UPAD, UPAD, 1024, down_b, x);
}

// round 3
// speedup vs baseline: 1.1514x; 1.1514x over previous
#include <cuda_runtime.h>
#include <cstdint>

// Problem constants
#define BB   8
#define TT   2048
#define DD   1024
#define HH   4
#define HSZ  256
#define KC   4
#define UU   1365
#define UPAD 1376          // U padded to multiple of 32 for tf32-MMA K tiling
#define BT   (BB*TT)       // 16384

#define SMS  36            // smem K-stride (floats): conflict-free fragment loads
#define BUFE (128*SMS)     // floats per tile buffer
#define GEMM_SMEM (4*BUFE*4)   // 2 bufs x (A+W) in bytes = 73728

// ---------------- scratch (static device globals; allocation-free rule) ----------
__device__ float g_xn    [BT * DD];            //  64 MB  layernormed x
__device__ float g_ifin  [BT * DD];            //  64 MB  swish(conv(xn))
__device__ float g_lin_if[(size_t)BT * 2048];  // 128 MB  weight_if @ ifin
__device__ float g_lin_zo[(size_t)BT * 2048];  // 128 MB  weight_zo @ xn
__device__ float g_zn    [BT * DD];            //  64 MB  post-scan groupnormed h
__device__ float g_up    [(size_t)BT * 2730];  // 179 MB  up projection (raw)
__device__ float g_act   [(size_t)BT * UPAD];  //  90 MB  gelu(u1)*u2 (zero-padded)
__device__ float g_whht  [HH * HSZ * DD];      //   4 MB  weight_hh transposed: [h][k][row]
__device__ float g_dwpad [DD * UPAD];          // 5.6 MB  down_w zero-padded to K=1376

// ---------------- LayerNorm over D=1024 per (b,t) row --------------------------
__global__ void ln_kernel(const float* __restrict__ x,
                          const float* __restrict__ lnw,
                          const float* __restrict__ lnb,
                          float* __restrict__ xn) {
    int row = blockIdx.x;
    int tid = threadIdx.x;           // 256 threads, 4 elems each
    const float4* xr = (const float4*)(x + (size_t)row * DD);
    float4 v = xr[tid];
    float s1 = v.x + v.y + v.z + v.w;
    float s2 = v.x*v.x + v.y*v.y + v.z*v.z + v.w*v.w;
    for (int o = 16; o; o >>= 1) {
        s1 += __shfl_xor_sync(0xffffffffu, s1, o);
        s2 += __shfl_xor_sync(0xffffffffu, s2, o);
    }
    __shared__ float rs1[8], rs2[8];
    if ((tid & 31) == 0) { rs1[tid >> 5] = s1; rs2[tid >> 5] = s2; }
    __syncthreads();
    float t1 = 0.f, t2 = 0.f;
#pragma unroll
    for (int w = 0; w < 8; w++) { t1 += rs1[w]; t2 += rs2[w]; }
    float mean = t1 * (1.0f / DD);
    float var  = t2 * (1.0f / DD) - mean * mean;
    float rstd = rsqrtf(var + 1e-5f);
    float4 wv = ((const float4*)lnw)[tid];
    float4 bv = ((const float4*)lnb)[tid];
    float4 o4;
    o4.x = (v.x - mean) * rstd * wv.x + bv.x;
    o4.y = (v.y - mean) * rstd * wv.y + bv.y;
    o4.z = (v.z - mean) * rstd * wv.z + bv.z;
    o4.w = (v.w - mean) * rstd * wv.w + bv.w;
    ((float4*)(xn + (size_t)row * DD))[tid] = o4;
}

// ---------------- causal depthwise conv (K=4 taps over t) + swish --------------
__global__ void conv_kernel(const float* __restrict__ xn,
                            const float* __restrict__ convw,   // (D,4) row-major
                            const float* __restrict__ convb,
                            float* __restrict__ ifin) {
    int idx = blockIdx.x * blockDim.x + threadIdx.x;   // over BT*DD
    if (idx >= BT * DD) return;
    int c  = idx & (DD - 1);
    int bt = idx >> 10;
    int t  = bt & (TT - 1);
    int b  = bt >> 11;
    float4 w4 = ((const float4*)convw)[c];
    const float wk[4] = { w4.x, w4.y, w4.z, w4.w };
    float acc = convb[c];
#pragma unroll
    for (int k = 0; k < KC; k++) {
        int tt = t - 3 + k;
        float xv = (tt >= 0) ? xn[((size_t)(b * TT + tt) << 10) + c] : 0.f;
        acc = fmaf(wk[k], xv, acc);
    }
    ifin[idx] = acc / (1.f + expf(-acc));   // swish
}

// ---------------- one-time weight prep kernels ---------------------------------
__global__ void twhh_kernel(const float* __restrict__ whh, float* __restrict__ whht) {
    int idx = blockIdx.x * blockDim.x + threadIdx.x;
    if (idx >= HH * HSZ * DD) return;
    int h   = idx >> 18;
    int rem = idx & 262143;
    int k   = rem >> 10;
    int r   = rem & 1023;
    whht[idx] = whh[((size_t)(h * DD + r)) * HSZ + k];
}

__global__ void pad_dw_kernel(const float* __restrict__ dw, float* __restrict__ out) {
    int idx = blockIdx.x * blockDim.x + threadIdx.x;   // DD*UPAD
    if (idx >= DD * UPAD) return;
    int r = idx / UPAD, k = idx - r * UPAD;
    out[idx] = (k < UU) ? dw[(size_t)r * UU + k] : 0.f;
}

// ---------------- recurrent scan: 32 CTAs = (b,h) lanes ------------------------
__global__ void __launch_bounds__(256) scan_kernel(
        const float* __restrict__ lin_if,
        const float* __restrict__ lin_zo,
        const float* __restrict__ whht,
        const float* __restrict__ bias,
        const float* __restrict__ gn_w,
        const float* __restrict__ gn_b,
        float* __restrict__ zn)
{
    int b   = blockIdx.x >> 2;
    int h   = blockIdx.x & 3;
    int tid = threadIdx.x;

    __shared__ float h_sm[HSZ];
    __shared__ float acc_sm[4 * HSZ];
    __shared__ float red_sm[16];

    h_sm[tid] = 0.f;
    float c_s = 0.f, n_s = 0.f, m_s = 0.f;

    const float* wt_base = whht + (size_t)h * HSZ * DD + 4 * tid;
    float b_i = bias[h * DD + tid];
    float b_f = bias[h * DD + 256 + tid];
    float b_z = bias[h * DD + 512 + tid];
    float b_o = bias[h * DD + 768 + tid];
    float gw  = gn_w[h * HSZ + tid];
    float gb  = gn_b[h * HSZ + tid];
    __syncthreads();

    for (int t = 0; t < TT; t++) {
        float4 acc4 = make_float4(0.f, 0.f, 0.f, 0.f);
        const float* wp = wt_base;
#pragma unroll 8
        for (int k = 0; k < HSZ; ++k) {
            float hk = h_sm[k];
            float4 w = *(const float4*)wp;
            acc4.x = fmaf(w.x, hk, acc4.x);
            acc4.y = fmaf(w.y, hk, acc4.y);
            acc4.z = fmaf(w.z, hk, acc4.z);
            acc4.w = fmaf(w.w, hk, acc4.w);
            wp += DD;
        }
        *(float4*)(acc_sm + 4 * tid) = acc4;
        __syncthreads();

        size_t row = (size_t)(b * TT + t);
        const float* lif = lin_if + row * 2048 + h * 512;
        const float* lzo = lin_zo + row * 2048 + h * 512;
        float iv = lif[tid]       + b_i + acc_sm[tid];
        float fv = lif[256 + tid] + b_f + acc_sm[256 + tid];
        float zv = lzo[tid]       + b_z + acc_sm[512 + tid];
        float ov = lzo[256 + tid] + b_o + acc_sm[768 + tid];
        float zg = tanhf(zv);
        float og = 1.f / (1.f + expf(-ov));
        float mn = fmaxf(fv + m_s, iv);
        float ie = expf(iv - mn);
        float fe = expf(fv + m_s - mn);
        c_s = fe * c_s + ie * zg;
        n_s = fe * n_s + ie;
        m_s = mn;
        float hval = og * (c_s / n_s);

        float s1 = hval, s2 = hval * hval;
        for (int o = 16; o; o >>= 1) {
            s1 += __shfl_xor_sync(0xffffffffu, s1, o);
            s2 += __shfl_xor_sync(0xffffffffu, s2, o);
        }
        if ((tid & 31) == 0) { red_sm[tid >> 5] = s1; red_sm[8 + (tid >> 5)] = s2; }
        __syncthreads();
        float t1 = 0.f, t2 = 0.f;
#pragma unroll
        for (int w = 0; w < 8; w++) { t1 += red_sm[w]; t2 += red_sm[8 + w]; }
        float mean = t1 * (1.0f / HSZ);
        float var  = t2 * (1.0f / HSZ) - mean * mean;
        float znv  = (hval - mean) * rsqrtf(var + 1e-5f) * gw + gb;
        zn[row * DD + h * HSZ + tid] = znv;

        h_sm[tid] = hval;
        __syncthreads();
    }
}

// ================= tf32 tensor-core GEMM =======================================
// C[m][n] = sum_k A[m][k] * W[n][k]   (A: MxK row-major, W: NxK row-major)
// MODE 0: plain  MODE 1: +bias[n]  MODE 2: +bias[n]+resid[m*ldc+n]
// 128x128 CTA tile, K-tile 32, 8 warps (2m x 4n), warp = 64x32 via m16n8k8.

__device__ __forceinline__ uint32_t f2tf32(float f) {
    uint32_t r;
    asm("cvt.rna.tf32.f32 %0, %1;" : "=r"(r) : "f"(f));
    return r;
}

__device__ __forceinline__ void mma_tf32(float c[4], const uint32_t a[4],
                                         const uint32_t b[2]) {
    asm volatile(
        "mma.sync.aligned.m16n8k8.row.col.f32.tf32.tf32.f32 "
        "{%0,%1,%2,%3},{%4,%5,%6,%7},{%8,%9},{%0,%1,%2,%3};\n"
        : "+f"(c[0]), "+f"(c[1]), "+f"(c[2]), "+f"(c[3])
        : "r"(a[0]), "r"(a[1]), "r"(a[2]), "r"(a[3]), "r"(b[0]), "r"(b[1]));
}

__device__ __forceinline__ void cp16(uint32_t dst, const void* src, int srcsize) {
    asm volatile("cp.async.cg.shared.global [%0], [%1], 16, %2;\n"
                 :: "r"(dst), "l"(src), "r"(srcsize));
}

template <int MODE>
__global__ void __launch_bounds__(256) gemm_mma(
        const float* __restrict__ A, const float* __restrict__ W,
        float* __restrict__ C,
        int M, int N, int K, int lda, int ldw, int ldc,
        const float* __restrict__ bias, const float* __restrict__ resid)
{
    extern __shared__ float sm[];
    uint32_t sbase = (uint32_t)__cvta_generic_to_shared(sm);
    // layout: A0 | A1 | W0 | W1 (each BUFE floats)
    const float* Abuf[2] = { sm,            sm + BUFE };
    const float* Wbuf[2] = { sm + 2*BUFE,   sm + 3*BUFE };

    int tid  = threadIdx.x;
    int warp = tid >> 5, lane = tid & 31;
    int g = lane >> 2, tig = lane & 3;
    int wm = (warp >> 2) * 64;    // 0 / 64
    int wn = (warp & 3) * 32;     // 0 / 32 / 64 / 96
    int bm = blockIdx.x * 128;
    int bn = blockIdx.y * 128;

    float acc[4][4][4];
#pragma unroll
    for (int mt = 0; mt < 4; mt++)
#pragma unroll
        for (int nt = 0; nt < 4; nt++)
#pragma unroll
            for (int r = 0; r < 4; r++) acc[mt][nt][r] = 0.f;

    int KT = K >> 5;   // K / 32

    // ---- tile loader (cp.async, zfill on W row tail) ----
    auto fill = [&](int kt, int buf) {
        int k0 = kt * 32;
        uint32_t sA = sbase + (uint32_t)(buf * BUFE) * 4u;
        uint32_t sW = sbase + (uint32_t)((2 + buf) * BUFE) * 4u;
#pragma unroll
        for (int i = 0; i < 4; i++) {
            int idx = tid + i * 256;          // 0..1023
            int row = idx >> 3;
            int c4  = idx & 7;
            uint32_t soff = (uint32_t)(row * SMS + c4 * 4) * 4u;
            const float* srcA = A + (size_t)(bm + row) * lda + k0 + c4 * 4;
            cp16(sA + soff, srcA, 16);
            int wr = bn + row;
            const float* srcW = W + (size_t)(wr < N ? wr : 0) * ldw + k0 + c4 * 4;
            cp16(sW + soff, srcW, wr < N ? 16 : 0);
        }
        asm volatile("cp.async.commit_group;\n");
    };

    fill(0, 0);

    for (int kt = 0; kt < KT; kt++) {
        int buf = kt & 1;
        if (kt + 1 < KT) {
            fill(kt + 1, buf ^ 1);
            asm volatile("cp.async.wait_group 1;\n");
        } else {
            asm volatile("cp.async.wait_group 0;\n");
        }
        __syncthreads();

        const float* Ab = Abuf[buf];
        const float* Wb = Wbuf[buf];
#pragma unroll
        for (int ks = 0; ks < 4; ks++) {
            int k0 = ks * 8;
            uint32_t afr[4][4];
#pragma unroll
            for (int mt = 0; mt < 4; mt++) {
                const float* p = Ab + (wm + mt * 16 + g) * SMS + k0 + tig;
                afr[mt][0] = f2tf32(p[0]);
                afr[mt][1] = f2tf32(p[8 * SMS]);
                afr[mt][2] = f2tf32(p[4]);
                afr[mt][3] = f2tf32(p[8 * SMS + 4]);
            }
            uint32_t bfr[4][2];
#pragma unroll
            for (int nt = 0; nt < 4; nt++) {
                const float* p = Wb + (wn + nt * 8 + g) * SMS + k0 + tig;
                bfr[nt][0] = f2tf32(p[0]);
                bfr[nt][1] = f2tf32(p[4]);
            }
#pragma unroll
            for (int mt = 0; mt < 4; mt++)
#pragma unroll
                for (int nt = 0; nt < 4; nt++)
                    mma_tf32(acc[mt][nt], afr[mt], bfr[nt]);
        }
        __syncthreads();
    }

    // ---- epilogue ----
#pragma unroll
    for (int mt = 0; mt < 4; mt++) {
        int m0 = bm + wm + mt * 16 + g;     // rows m0 and m0+8
#pragma unroll
        for (int nt = 0; nt < 4; nt++) {
            int n0 = bn + wn + nt * 8 + 2 * tig;
            if (n0 < N) {
                float v0 = acc[mt][nt][0];
                float v1 = acc[mt][nt][1];
                float v2 = acc[mt][nt][2];
                float v3 = acc[mt][nt][3];
                if (MODE >= 1) {
                    float bz0 = bias[n0], bz1 = bias[n0 + 1];
                    v0 += bz0; v1 += bz1; v2 += bz0; v3 += bz1;
                }
                if (MODE == 2) {
                    v0 += resid[(size_t)m0 * ldc + n0];
                    v1 += resid[(size_t)m0 * ldc + n0 + 1];
                    v2 += resid[(size_t)(m0 + 8) * ldc + n0];
                    v3 += resid[(size_t)(m0 + 8) * ldc + n0 + 1];
                }
                C[(size_t)m0 * ldc + n0]           = v0;
                C[(size_t)m0 * ldc + n0 + 1]       = v1;
                C[(size_t)(m0 + 8) * ldc + n0]     = v2;
                C[(size_t)(m0 + 8) * ldc + n0 + 1] = v3;
            }
        }
    }
}

// ---------------- gelu(u1)*u2 with zero-padding to UPAD ------------------------
__global__ void act_kernel(const float* __restrict__ up, float* __restrict__ act) {
    int idx = blockIdx.x * blockDim.x + threadIdx.x;   // over BT*UPAD
    if (idx >= BT * UPAD) return;
    int row = idx / UPAD, j = idx - row * UPAD;
    float v = 0.f;
    if (j < UU) {
        float u1 = up[(size_t)row * 2730 + j];
        float u2 = up[(size_t)row * 2730 + UU + j];
        float gelu = 0.5f * u1 * (1.f + tanhf(0.7978845608028654f *
                                              (u1 + 0.044715f * u1 * u1 * u1)));
        v = gelu * u2;
    }
    act[idx] = v;
}

// ---------------- launch ---------------------------------------------------------
extern "C" void kernel_launch(void* const* d_in, const int* in_sizes, int n_in,
                              void* d_out, int out_size) {
    const float* x      = (const float*)d_in[0];
    const float* ln_w   = (const float*)d_in[1];
    const float* ln_b   = (const float*)d_in[2];
    const float* conv_w = (const float*)d_in[3];
    const float* conv_b = (const float*)d_in[4];
    const float* w_if   = (const float*)d_in[5];
    const float* w_zo   = (const float*)d_in[6];
    const float* w_hh   = (const float*)d_in[7];
    const float* bias   = (const float*)d_in[8];
    const float* gn_w   = (const float*)d_in[9];
    const float* gn_b   = (const float*)d_in[10];
    const float* up_w   = (const float*)d_in[11];
    const float* up_b   = (const float*)d_in[12];
    const float* down_w = (const float*)d_in[13];
    const float* down_b = (const float*)d_in[14];
    float* out = (float*)d_out;

    static float *p_xn = nullptr, *p_ifin, *p_lif, *p_lzo, *p_zn, *p_up, *p_act,
                 *p_whht, *p_dwpad;
    if (!p_xn) {
        cudaGetSymbolAddress((void**)&p_xn,    g_xn);
        cudaGetSymbolAddress((void**)&p_ifin,  g_ifin);
        cudaGetSymbolAddress((void**)&p_lif,   g_lin_if);
        cudaGetSymbolAddress((void**)&p_lzo,   g_lin_zo);
        cudaGetSymbolAddress((void**)&p_zn,    g_zn);
        cudaGetSymbolAddress((void**)&p_up,    g_up);
        cudaGetSymbolAddress((void**)&p_act,   g_act);
        cudaGetSymbolAddress((void**)&p_whht,  g_whht);
        cudaGetSymbolAddress((void**)&p_dwpad, g_dwpad);
        cudaFuncSetAttribute(gemm_mma<0>,
            cudaFuncAttributeMaxDynamicSharedMemorySize, GEMM_SMEM);
        cudaFuncSetAttribute(gemm_mma<1>,
            cudaFuncAttributeMaxDynamicSharedMemorySize, GEMM_SMEM);
        cudaFuncSetAttribute(gemm_mma<2>,
            cudaFuncAttributeMaxDynamicSharedMemorySize, GEMM_SMEM);
    }

    // weight prep
    twhh_kernel  <<<(HH * HSZ * DD + 255) / 256, 256>>>(w_hh, p_whht);
    pad_dw_kernel<<<(DD * UPAD + 255) / 256, 256>>>(down_w, p_dwpad);

    // Phase A: LN -> conv+swish -> two big tf32 GEMMs
    ln_kernel  <<<BT, 256>>>(x, ln_w, ln_b, p_xn);
    conv_kernel<<<(BT * DD + 255) / 256, 256>>>(p_xn, conv_w, conv_b, p_ifin);
    gemm_mma<0><<<dim3(BT / 128, 2048 / 128), 256, GEMM_SMEM>>>(
        p_ifin, w_if, p_lif, BT, 2048, 1024, 1024, 1024, 2048, nullptr, nullptr);
    gemm_mma<0><<<dim3(BT / 128, 2048 / 128), 256, GEMM_SMEM>>>(
        p_xn, w_zo, p_lzo, BT, 2048, 1024, 1024, 1024, 2048, nullptr, nullptr);

    // Phase B: sequential sLSTM scan, 32 independent (batch, head) lanes
    scan_kernel<<<32, 256>>>(p_lif, p_lzo, p_whht, bias, gn_w, gn_b, p_zn);

    // Phase C: MLP as tf32 GEMMs + fused bias/residual
    gemm_mma<1><<<dim3(BT / 128, (2730 + 127) / 128), 256, GEMM_SMEM>>>(
        p_zn, up_w, p_up, BT, 2730, 1024, 1024, 1024, 2730, up_b, nullptr);
    act_kernel<<<(BT * UPAD + 255) / 256, 256>>>(p_up, p_act);
    gemm_mma<2><<<dim3(BT / 128, 1024 / 128), 256, GEMM_SMEM>>>(
        p_act, p_dwpad, out, BT, 1024, UPAD, UPAD, UPAD, 1024, down_b, x);
}

// round 4
// speedup vs baseline: 2.4607x; 2.1372x over previous
#include <cuda_runtime.h>
#include <cstdint>

// Problem constants
#define BB   8
#define TT   2048
#define DD   1024
#define HH   4
#define HSZ  256
#define KC   4
#define UU   1365
#define UPAD 1376          // U padded to multiple of 32 for tf32-MMA K tiling
#define BT   (BB*TT)       // 16384

#define SMS  36            // smem K-stride (floats): conflict-free fragment loads
#define BUFE (128*SMS)     // floats per tile buffer
#define GEMM_SMEM (4*BUFE*4)   // 2 bufs x (A+W) in bytes = 73728

// ---------------- scratch (static device globals; allocation-free rule) ----------
__device__ float g_xn    [BT * DD];
__device__ float g_ifin  [BT * DD];
__device__ float g_lin_if[(size_t)BT * 2048];
__device__ float g_lin_zo[(size_t)BT * 2048];
__device__ float g_zn    [BT * DD];
__device__ float g_up    [(size_t)BT * 2730];
__device__ float g_act   [(size_t)BT * UPAD];
__device__ float g_whht  [HH * HSZ * DD];      // weight_hh transposed: [h][k][row]
__device__ float g_dwpad [DD * UPAD];

// ---------------- LayerNorm over D=1024 per (b,t) row --------------------------
__global__ void ln_kernel(const float* __restrict__ x,
                          const float* __restrict__ lnw,
                          const float* __restrict__ lnb,
                          float* __restrict__ xn) {
    int row = blockIdx.x;
    int tid = threadIdx.x;
    const float4* xr = (const float4*)(x + (size_t)row * DD);
    float4 v = xr[tid];
    float s1 = v.x + v.y + v.z + v.w;
    float s2 = v.x*v.x + v.y*v.y + v.z*v.z + v.w*v.w;
    for (int o = 16; o; o >>= 1) {
        s1 += __shfl_xor_sync(0xffffffffu, s1, o);
        s2 += __shfl_xor_sync(0xffffffffu, s2, o);
    }
    __shared__ float rs1[8], rs2[8];
    if ((tid & 31) == 0) { rs1[tid >> 5] = s1; rs2[tid >> 5] = s2; }
    __syncthreads();
    float t1 = 0.f, t2 = 0.f;
#pragma unroll
    for (int w = 0; w < 8; w++) { t1 += rs1[w]; t2 += rs2[w]; }
    float mean = t1 * (1.0f / DD);
    float var  = t2 * (1.0f / DD) - mean * mean;
    float rstd = rsqrtf(var + 1e-5f);
    float4 wv = ((const float4*)lnw)[tid];
    float4 bv = ((const float4*)lnb)[tid];
    float4 o4;
    o4.x = (v.x - mean) * rstd * wv.x + bv.x;
    o4.y = (v.y - mean) * rstd * wv.y + bv.y;
    o4.z = (v.z - mean) * rstd * wv.z + bv.z;
    o4.w = (v.w - mean) * rstd * wv.w + bv.w;
    ((float4*)(xn + (size_t)row * DD))[tid] = o4;
}

// ---------------- causal depthwise conv (K=4 taps over t) + swish --------------
__global__ void conv_kernel(const float* __restrict__ xn,
                            const float* __restrict__ convw,
                            const float* __restrict__ convb,
                            float* __restrict__ ifin) {
    int idx = blockIdx.x * blockDim.x + threadIdx.x;
    if (idx >= BT * DD) return;
    int c  = idx & (DD - 1);
    int bt = idx >> 10;
    int t  = bt & (TT - 1);
    int b  = bt >> 11;
    float4 w4 = ((const float4*)convw)[c];
    const float wk[4] = { w4.x, w4.y, w4.z, w4.w };
    float acc = convb[c];
#pragma unroll
    for (int k = 0; k < KC; k++) {
        int tt = t - 3 + k;
        float xv = (tt >= 0) ? xn[((size_t)(b * TT + tt) << 10) + c] : 0.f;
        acc = fmaf(wk[k], xv, acc);
    }
    ifin[idx] = acc / (1.f + expf(-acc));
}

// ---------------- one-time weight prep kernels ---------------------------------
__global__ void twhh_kernel(const float* __restrict__ whh, float* __restrict__ whht) {
    int idx = blockIdx.x * blockDim.x + threadIdx.x;
    if (idx >= HH * HSZ * DD) return;
    int h   = idx >> 18;
    int rem = idx & 262143;
    int k   = rem >> 10;
    int r   = rem & 1023;
    whht[idx] = whh[((size_t)(h * DD + r)) * HSZ + k];
}

__global__ void pad_dw_kernel(const float* __restrict__ dw, float* __restrict__ out) {
    int idx = blockIdx.x * blockDim.x + threadIdx.x;
    if (idx >= DD * UPAD) return;
    int r = idx / UPAD, k = idx - r * UPAD;
    out[idx] = (k < UU) ? dw[(size_t)r * UU + k] : 0.f;
}

// ---------------- recurrent scan: 32 CTAs = (b,h) lanes ------------------------
// v2: software-pipelined matvec. Each thread owns rows 4t..4t+3; per step it
// streams 256 float4 (k-major weights) with an explicit 2x8 register ping-pong
// so 8 LDG.128 are always in flight while the previous 8 are consumed.
__global__ void __launch_bounds__(256) scan_kernel(
        const float* __restrict__ lin_if,
        const float* __restrict__ lin_zo,
        const float* __restrict__ whht,
        const float* __restrict__ bias,
        const float* __restrict__ gn_w,
        const float* __restrict__ gn_b,
        float* __restrict__ zn)
{
    int b   = blockIdx.x >> 2;
    int h   = blockIdx.x & 3;
    int tid = threadIdx.x;

    __shared__ float h_sm[HSZ];
    __shared__ float acc_sm[4 * HSZ];
    __shared__ float red_sm[16];

    h_sm[tid] = 0.f;
    float c_s = 0.f, n_s = 0.f, m_s = 0.f;

    const float* wt_base = whht + (size_t)h * HSZ * DD + 4 * tid;
    float b_i = bias[h * DD + tid];
    float b_f = bias[h * DD + 256 + tid];
    float b_z = bias[h * DD + 512 + tid];
    float b_o = bias[h * DD + 768 + tid];
    float gw  = gn_w[h * HSZ + tid];
    float gb  = gn_b[h * HSZ + tid];
    __syncthreads();

    for (int t = 0; t < TT; t++) {
        size_t row = (size_t)(b * TT + t);
        const float* lif = lin_if + row * 2048 + h * 512;
        const float* lzo = lin_zo + row * 2048 + h * 512;
        // prefetch gate operands (DRAM) — latency hides under the matvec
        float pre_i = lif[tid];
        float pre_f = lif[256 + tid];
        float pre_z = lzo[tid];
        float pre_o = lzo[256 + tid];

        // ---- pipelined matvec: rows 4tid..4tid+3, k = 0..255 ----
        float4 bufA[8], bufB[8];
        float4 acc4 = make_float4(0.f, 0.f, 0.f, 0.f);
        {
            const float* wp = wt_base;
#pragma unroll
            for (int j = 0; j < 8; j++)
                bufA[j] = *(const float4*)(wp + (size_t)j * DD);
        }
#pragma unroll 1
        for (int c0 = 0; c0 < 256; c0 += 16) {
            const float* wq = wt_base + (size_t)(c0 + 8) * DD;
#pragma unroll
            for (int j = 0; j < 8; j++)
                bufB[j] = *(const float4*)(wq + (size_t)j * DD);
#pragma unroll
            for (int j = 0; j < 8; j++) {
                float hk = h_sm[c0 + j];
                acc4.x = fmaf(bufA[j].x, hk, acc4.x);
                acc4.y = fmaf(bufA[j].y, hk, acc4.y);
                acc4.z = fmaf(bufA[j].z, hk, acc4.z);
                acc4.w = fmaf(bufA[j].w, hk, acc4.w);
            }
            if (c0 + 16 < 256) {
                const float* wr = wt_base + (size_t)(c0 + 16) * DD;
#pragma unroll
                for (int j = 0; j < 8; j++)
                    bufA[j] = *(const float4*)(wr + (size_t)j * DD);
            }
#pragma unroll
            for (int j = 0; j < 8; j++) {
                float hk = h_sm[c0 + 8 + j];
                acc4.x = fmaf(bufB[j].x, hk, acc4.x);
                acc4.y = fmaf(bufB[j].y, hk, acc4.y);
                acc4.z = fmaf(bufB[j].z, hk, acc4.z);
                acc4.w = fmaf(bufB[j].w, hk, acc4.w);
            }
        }
        *(float4*)(acc_sm + 4 * tid) = acc4;
        __syncthreads();

        // gates for HS index s = tid
        float iv = pre_i + b_i + acc_sm[tid];
        float fv = pre_f + b_f + acc_sm[256 + tid];
        float zv = pre_z + b_z + acc_sm[512 + tid];
        float ov = pre_o + b_o + acc_sm[768 + tid];
        float zg = tanhf(zv);
        float og = 1.f / (1.f + __expf(-ov));
        float mn = fmaxf(fv + m_s, iv);
        float ie = __expf(iv - mn);
        float fe = __expf(fv + m_s - mn);
        c_s = fe * c_s + ie * zg;
        n_s = fe * n_s + ie;
        m_s = mn;
        float hval = og * (c_s / n_s);

        // groupnorm over the head's 256 values
        float s1 = hval, s2 = hval * hval;
        for (int o = 16; o; o >>= 1) {
            s1 += __shfl_xor_sync(0xffffffffu, s1, o);
            s2 += __shfl_xor_sync(0xffffffffu, s2, o);
        }
        if ((tid & 31) == 0) { red_sm[tid >> 5] = s1; red_sm[8 + (tid >> 5)] = s2; }
        __syncthreads();
        float t1 = 0.f, t2 = 0.f;
#pragma unroll
        for (int w = 0; w < 8; w++) { t1 += red_sm[w]; t2 += red_sm[8 + w]; }
        float mean = t1 * (1.0f / HSZ);
        float var  = t2 * (1.0f / HSZ) - mean * mean;
        float znv  = (hval - mean) * rsqrtf(var + 1e-5f) * gw + gb;
        zn[row * DD + h * HSZ + tid] = znv;

        h_sm[tid] = hval;
        __syncthreads();
    }
}

// ================= tf32 tensor-core GEMM (unchanged from R2) ====================
__device__ __forceinline__ uint32_t f2tf32(float f) {
    uint32_t r;
    asm("cvt.rna.tf32.f32 %0, %1;" : "=r"(r) : "f"(f));
    return r;
}

__device__ __forceinline__ void mma_tf32(float c[4], const uint32_t a[4],
                                         const uint32_t b[2]) {
    asm volatile(
        "mma.sync.aligned.m16n8k8.row.col.f32.tf32.tf32.f32 "
        "{%0,%1,%2,%3},{%4,%5,%6,%7},{%8,%9},{%0,%1,%2,%3};\n"
        : "+f"(c[0]), "+f"(c[1]), "+f"(c[2]), "+f"(c[3])
        : "r"(a[0]), "r"(a[1]), "r"(a[2]), "r"(a[3]), "r"(b[0]), "r"(b[1]));
}

__device__ __forceinline__ void cp16(uint32_t dst, const void* src, int srcsize) {
    asm volatile("cp.async.cg.shared.global [%0], [%1], 16, %2;\n"
                 :: "r"(dst), "l"(src), "r"(srcsize));
}

template <int MODE>
__global__ void __launch_bounds__(256) gemm_mma(
        const float* __restrict__ A, const float* __restrict__ W,
        float* __restrict__ C,
        int M, int N, int K, int lda, int ldw, int ldc,
        const float* __restrict__ bias, const float* __restrict__ resid)
{
    extern __shared__ float sm[];
    uint32_t sbase = (uint32_t)__cvta_generic_to_shared(sm);
    const float* Abuf[2] = { sm,            sm + BUFE };
    const float* Wbuf[2] = { sm + 2*BUFE,   sm + 3*BUFE };

    int tid  = threadIdx.x;
    int warp = tid >> 5, lane = tid & 31;
    int g = lane >> 2, tig = lane & 3;
    int wm = (warp >> 2) * 64;
    int wn = (warp & 3) * 32;
    int bm = blockIdx.x * 128;
    int bn = blockIdx.y * 128;

    float acc[4][4][4];
#pragma unroll
    for (int mt = 0; mt < 4; mt++)
#pragma unroll
        for (int nt = 0; nt < 4; nt++)
#pragma unroll
            for (int r = 0; r < 4; r++) acc[mt][nt][r] = 0.f;

    int KT = K >> 5;

    auto fill = [&](int kt, int buf) {
        int k0 = kt * 32;
        uint32_t sA = sbase + (uint32_t)(buf * BUFE) * 4u;
        uint32_t sW = sbase + (uint32_t)((2 + buf) * BUFE) * 4u;
#pragma unroll
        for (int i = 0; i < 4; i++) {
            int idx = tid + i * 256;
            int row = idx >> 3;
            int c4  = idx & 7;
            uint32_t soff = (uint32_t)(row * SMS + c4 * 4) * 4u;
            const float* srcA = A + (size_t)(bm + row) * lda + k0 + c4 * 4;
            cp16(sA + soff, srcA, 16);
            int wr = bn + row;
            const float* srcW = W + (size_t)(wr < N ? wr : 0) * ldw + k0 + c4 * 4;
            cp16(sW + soff, srcW, wr < N ? 16 : 0);
        }
        asm volatile("cp.async.commit_group;\n");
    };

    fill(0, 0);

    for (int kt = 0; kt < KT; kt++) {
        int buf = kt & 1;
        if (kt + 1 < KT) {
            fill(kt + 1, buf ^ 1);
            asm volatile("cp.async.wait_group 1;\n");
        } else {
            asm volatile("cp.async.wait_group 0;\n");
        }
        __syncthreads();

        const float* Ab = Abuf[buf];
        const float* Wb = Wbuf[buf];
#pragma unroll
        for (int ks = 0; ks < 4; ks++) {
            int k0 = ks * 8;
            uint32_t afr[4][4];
#pragma unroll
            for (int mt = 0; mt < 4; mt++) {
                const float* p = Ab + (wm + mt * 16 + g) * SMS + k0 + tig;
                afr[mt][0] = f2tf32(p[0]);
                afr[mt][1] = f2tf32(p[8 * SMS]);
                afr[mt][2] = f2tf32(p[4]);
                afr[mt][3] = f2tf32(p[8 * SMS + 4]);
            }
            uint32_t bfr[4][2];
#pragma unroll
            for (int nt = 0; nt < 4; nt++) {
                const float* p = Wb + (wn + nt * 8 + g) * SMS + k0 + tig;
                bfr[nt][0] = f2tf32(p[0]);
                bfr[nt][1] = f2tf32(p[4]);
            }
#pragma unroll
            for (int mt = 0; mt < 4; mt++)
#pragma unroll
                for (int nt = 0; nt < 4; nt++)
                    mma_tf32(acc[mt][nt], afr[mt], bfr[nt]);
        }
        __syncthreads();
    }

#pragma unroll
    for (int mt = 0; mt < 4; mt++) {
        int m0 = bm + wm + mt * 16 + g;
#pragma unroll
        for (int nt = 0; nt < 4; nt++) {
            int n0 = bn + wn + nt * 8 + 2 * tig;
            if (n0 < N) {
                float v0 = acc[mt][nt][0];
                float v1 = acc[mt][nt][1];
                float v2 = acc[mt][nt][2];
                float v3 = acc[mt][nt][3];
                if (MODE >= 1) {
                    float bz0 = bias[n0], bz1 = bias[n0 + 1];
                    v0 += bz0; v1 += bz1; v2 += bz0; v3 += bz1;
                }
                if (MODE == 2) {
                    v0 += resid[(size_t)m0 * ldc + n0];
                    v1 += resid[(size_t)m0 * ldc + n0 + 1];
                    v2 += resid[(size_t)(m0 + 8) * ldc + n0];
                    v3 += resid[(size_t)(m0 + 8) * ldc + n0 + 1];
                }
                C[(size_t)m0 * ldc + n0]           = v0;
                C[(size_t)m0 * ldc + n0 + 1]       = v1;
                C[(size_t)(m0 + 8) * ldc + n0]     = v2;
                C[(size_t)(m0 + 8) * ldc + n0 + 1] = v3;
            }
        }
    }
}

// ---------------- gelu(u1)*u2 with zero-padding to UPAD ------------------------
__global__ void act_kernel(const float* __restrict__ up, float* __restrict__ act) {
    int idx = blockIdx.x * blockDim.x + threadIdx.x;
    if (idx >= BT * UPAD) return;
    int row = idx / UPAD, j = idx - row * UPAD;
    float v = 0.f;
    if (j < UU) {
        float u1 = up[(size_t)row * 2730 + j];
        float u2 = up[(size_t)row * 2730 + UU + j];
        float gelu = 0.5f * u1 * (1.f + tanhf(0.7978845608028654f *
                                              (u1 + 0.044715f * u1 * u1 * u1)));
        v = gelu * u2;
    }
    act[idx] = v;
}

// ---------------- launch ---------------------------------------------------------
extern "C" void kernel_launch(void* const* d_in, const int* in_sizes, int n_in,
                              void* d_out, int out_size) {
    const float* x      = (const float*)d_in[0];
    const float* ln_w   = (const float*)d_in[1];
    const float* ln_b   = (const float*)d_in[2];
    const float* conv_w = (const float*)d_in[3];
    const float* conv_b = (const float*)d_in[4];
    const float* w_if   = (const float*)d_in[5];
    const float* w_zo   = (const float*)d_in[6];
    const float* w_hh   = (const float*)d_in[7];
    const float* bias   = (const float*)d_in[8];
    const float* gn_w   = (const float*)d_in[9];
    const float* gn_b   = (const float*)d_in[10];
    const float* up_w   = (const float*)d_in[11];
    const float* up_b   = (const float*)d_in[12];
    const float* down_w = (const float*)d_in[13];
    const float* down_b = (const float*)d_in[14];
    float* out = (float*)d_out;

    static float *p_xn = nullptr, *p_ifin, *p_lif, *p_lzo, *p_zn, *p_up, *p_act,
                 *p_whht, *p_dwpad;
    if (!p_xn) {
        cudaGetSymbolAddress((void**)&p_xn,    g_xn);
        cudaGetSymbolAddress((void**)&p_ifin,  g_ifin);
        cudaGetSymbolAddress((void**)&p_lif,   g_lin_if);
        cudaGetSymbolAddress((void**)&p_lzo,   g_lin_zo);
        cudaGetSymbolAddress((void**)&p_zn,    g_zn);
        cudaGetSymbolAddress((void**)&p_up,    g_up);
        cudaGetSymbolAddress((void**)&p_act,   g_act);
        cudaGetSymbolAddress((void**)&p_whht,  g_whht);
        cudaGetSymbolAddress((void**)&p_dwpad, g_dwpad);
        cudaFuncSetAttribute(gemm_mma<0>,
            cudaFuncAttributeMaxDynamicSharedMemorySize, GEMM_SMEM);
        cudaFuncSetAttribute(gemm_mma<1>,
            cudaFuncAttributeMaxDynamicSharedMemorySize, GEMM_SMEM);
        cudaFuncSetAttribute(gemm_mma<2>,
            cudaFuncAttributeMaxDynamicSharedMemorySize, GEMM_SMEM);
    }

    // Launch order arranged so the ncu capture (skip 5, profile 1) lands on
    // scan_kernel (launch #6).
    ln_kernel  <<<BT, 256>>>(x, ln_w, ln_b, p_xn);                                  // 1
    conv_kernel<<<(BT * DD + 255) / 256, 256>>>(p_xn, conv_w, conv_b, p_ifin);      // 2
    gemm_mma<0><<<dim3(BT / 128, 2048 / 128), 256, GEMM_SMEM>>>(                    // 3
        p_ifin, w_if, p_lif, BT, 2048, 1024, 1024, 1024, 2048, nullptr, nullptr);
    gemm_mma<0><<<dim3(BT / 128, 2048 / 128), 256, GEMM_SMEM>>>(                    // 4
        p_xn, w_zo, p_lzo, BT, 2048, 1024, 1024, 1024, 2048, nullptr, nullptr);
    twhh_kernel<<<(HH * HSZ * DD + 255) / 256, 256>>>(w_hh, p_whht);                // 5
    scan_kernel<<<32, 256>>>(p_lif, p_lzo, p_whht, bias, gn_w, gn_b, p_zn);         // 6 (profiled)
    pad_dw_kernel<<<(DD * UPAD + 255) / 256, 256>>>(down_w, p_dwpad);               // 7
    gemm_mma<1><<<dim3(BT / 128, (2730 + 127) / 128), 256, GEMM_SMEM>>>(            // 8
        p_zn, up_w, p_up, BT, 2730, 1024, 1024, 1024, 2730, up_b, nullptr);
    act_kernel<<<(BT * UPAD + 255) / 256, 256>>>(p_up, p_act);                      // 9
    gemm_mma<2><<<dim3(BT / 128, 1024 / 128), 256, GEMM_SMEM>>>(                    // 10
        p_act, p_dwpad, out, BT, 1024, UPAD, UPAD, UPAD, 1024, down_b, x);
}

// round 5
// speedup vs baseline: 3.9606x; 1.6096x over previous
#include <cuda_runtime.h>
#include <cstdint>

// Problem constants
#define BB   8
#define TT   2048
#define DD   1024
#define HH   4
#define HSZ  256
#define KC   4
#define UU   1365
#define UPAD 1376
#define BT   (BB*TT)       // 16384

#define SMS  36            // gemm smem K-stride
#define BUFE (128*SMS)
#define GEMM_SMEM (4*BUFE*4)

// ---------------- scratch ----------------
__device__ float g_xn    [BT * DD];
__device__ float g_ifin  [BT * DD];
__device__ float g_lin_if[(size_t)BT * 2048];
__device__ float g_lin_zo[(size_t)BT * 2048];
__device__ float g_zn    [BT * DD];
__device__ float g_up    [(size_t)BT * 2730];
__device__ float g_act   [(size_t)BT * UPAD];
__device__ float g_dwpad [DD * UPAD];

// ---------------- LayerNorm --------------------------------------------------
__global__ void ln_kernel(const float* __restrict__ x,
                          const float* __restrict__ lnw,
                          const float* __restrict__ lnb,
                          float* __restrict__ xn) {
    int row = blockIdx.x;
    int tid = threadIdx.x;
    const float4* xr = (const float4*)(x + (size_t)row * DD);
    float4 v = xr[tid];
    float s1 = v.x + v.y + v.z + v.w;
    float s2 = v.x*v.x + v.y*v.y + v.z*v.z + v.w*v.w;
    for (int o = 16; o; o >>= 1) {
        s1 += __shfl_xor_sync(0xffffffffu, s1, o);
        s2 += __shfl_xor_sync(0xffffffffu, s2, o);
    }
    __shared__ float rs1[8], rs2[8];
    if ((tid & 31) == 0) { rs1[tid >> 5] = s1; rs2[tid >> 5] = s2; }
    __syncthreads();
    float t1 = 0.f, t2 = 0.f;
#pragma unroll
    for (int w = 0; w < 8; w++) { t1 += rs1[w]; t2 += rs2[w]; }
    float mean = t1 * (1.0f / DD);
    float var  = t2 * (1.0f / DD) - mean * mean;
    float rstd = rsqrtf(var + 1e-5f);
    float4 wv = ((const float4*)lnw)[tid];
    float4 bv = ((const float4*)lnb)[tid];
    float4 o4;
    o4.x = (v.x - mean) * rstd * wv.x + bv.x;
    o4.y = (v.y - mean) * rstd * wv.y + bv.y;
    o4.z = (v.z - mean) * rstd * wv.z + bv.z;
    o4.w = (v.w - mean) * rstd * wv.w + bv.w;
    ((float4*)(xn + (size_t)row * DD))[tid] = o4;
}

// ---------------- causal depthwise conv + swish ------------------------------
__global__ void conv_kernel(const float* __restrict__ xn,
                            const float* __restrict__ convw,
                            const float* __restrict__ convb,
                            float* __restrict__ ifin) {
    int idx = blockIdx.x * blockDim.x + threadIdx.x;
    if (idx >= BT * DD) return;
    int c  = idx & (DD - 1);
    int bt = idx >> 10;
    int t  = bt & (TT - 1);
    int b  = bt >> 11;
    float4 w4 = ((const float4*)convw)[c];
    const float wk[4] = { w4.x, w4.y, w4.z, w4.w };
    float acc = convb[c];
#pragma unroll
    for (int k = 0; k < KC; k++) {
        int tt = t - 3 + k;
        float xv = (tt >= 0) ? xn[((size_t)(b * TT + tt) << 10) + c] : 0.f;
        acc = fmaf(wk[k], xv, acc);
    }
    ifin[idx] = acc / (1.f + expf(-acc));
}

__global__ void pad_dw_kernel(const float* __restrict__ dw, float* __restrict__ out) {
    int idx = blockIdx.x * blockDim.x + threadIdx.x;
    if (idx >= DD * UPAD) return;
    int r = idx / UPAD, k = idx - r * UPAD;
    out[idx] = (k < UU) ? dw[(size_t)r * UU + k] : 0.f;
}

// ---------------- recurrent scan: cluster-8, register-resident weights --------
// grid = 128 CTAs = 16 clusters of 8. Cluster cl: head h = cl&3, batch pair
// q = cl>>2 -> batches (2q, 2q+1). CTA rank jj owns s-indices jj*32..jj*32+31
// (all 4 gates = 128 rows x 256 k = 128KB held in registers, 128/thread).
// Per step: reg-x-smem matvec for both batches; h_new pushed to all 8 peers'
// smem via mapa/st.shared::cluster; one barrier.cluster per step.
__device__ __forceinline__ uint32_t smem_u32(const void* p) {
    return (uint32_t)__cvta_generic_to_shared(p);
}

__global__ void __launch_bounds__(256, 1) __cluster_dims__(8, 1, 1)
scan_kernel(const float* __restrict__ lin_if,
            const float* __restrict__ lin_zo,
            const float* __restrict__ whh,     // [H][1024][256] original layout
            const float* __restrict__ bias,    // [H][1024]
            const float* __restrict__ gn_w,
            const float* __restrict__ gn_b,
            float* __restrict__ zn)
{
    int cl = blockIdx.x >> 3;         // cluster id 0..15
    int jj = blockIdx.x & 7;          // rank in cluster
    int h  = cl & 3;
    int q  = cl >> 2;
    int b0 = 2 * q, b1 = 2 * q + 1;

    int tid  = threadIdx.x;           // 256
    int r    = tid & 127;             // row in slice: gate = r>>5, sl = r&31
    int half = tid >> 7;              // k-half (0: k 0..127, 1: k 128..255)
    int wrp  = tid >> 5, lane = tid & 31;

    __shared__ __align__(16) float hbuf[2][256][2];   // [parity][k][batch]
    __shared__ float part_sm[2][256];                 // matvec partials
    __shared__ float lt_sm[2][128];                   // lin totals per batch
    __shared__ float h_loc[2][32];
    __shared__ float my_sums[4];                      // s1b0,s2b0,s1b1,s2b1
    __shared__ float sumbuf[2][32];                   // [parity][peer*4+item]

    // ---- load weight slice into registers ----
    float w[128];
    {
        int gate = r >> 5, sl = r & 31;
        int rowg = gate * 256 + jj * 32 + sl;                 // 0..1023
        const float* src = whh + ((size_t)(h * 1024 + rowg)) * 256 + half * 128;
#pragma unroll
        for (int i = 0; i < 32; i++) {
            float4 v = *(const float4*)(src + 4 * i);
            w[4*i] = v.x; w[4*i+1] = v.y; w[4*i+2] = v.z; w[4*i+3] = v.w;
        }
    }

    // per-lane constants for gate threads (warps 0/1, lane = sl)
    int s_loc = jj * 32 + lane;                                // s in 0..255
    float gw = gn_w[h * HSZ + s_loc];
    float gb = gn_b[h * HSZ + s_loc];
    // bias for assembly threads (tid<128 own row r)
    float bias_r = bias[h * 1024 + (r >> 5) * 256 + jj * 32 + (r & 31)];

    // init h parity-0 buffer and state
    hbuf[0][tid][0] = 0.f;
    if (tid < 256) { hbuf[0][tid][1] = 0.f; }
    float c_s = 0.f, n_s = 0.f, m_s = 0.f;   // live in warps 0/1 lanes
    __syncthreads();

    const float* lifb0 = lin_if + (size_t)b0 * TT * 2048 + h * 512;
    const float* lifb1 = lin_if + (size_t)b1 * TT * 2048 + h * 512;
    const float* lzob0 = lin_zo + (size_t)b0 * TT * 2048 + h * 512;
    const float* lzob1 = lin_zo + (size_t)b1 * TT * 2048 + h * 512;

    for (int t = 0; t < TT; t++) {
        int pb = t & 1, nb = pb ^ 1;

        // ---- prefetch gate linear inputs (DRAM) for both batches ----
        float pre0 = 0.f, pre1 = 0.f;
        if (tid < 128) {
            int gate = r >> 5, sl = r & 31;
            int s = jj * 32 + sl;
            size_t off = (size_t)t * 2048;
            int col = (gate & 1) * 256 + s;
            if (gate < 2) {            // i, f from lin_if
                pre0 = lifb0[off + col];
                pre1 = lifb1[off + col];
            } else {                   // z, o from lin_zo
                pre0 = lzob0[off + col];
                pre1 = lzob1[off + col];
            }
        }

        // ---- matvec: 128 k-values x 2 batches, weights in regs ----
        int kbase = half * 128;
        float a0=0.f,a1=0.f,a2=0.f,a3=0.f;     // batch0
        float c0=0.f,c1=0.f,c2=0.f,c3=0.f;     // batch1
#pragma unroll
        for (int kk = 0; kk < 128; kk += 4) {
            float4 p = *(const float4*)&hbuf[pb][kbase + kk][0];     // h0k,h1k,h0k1,h1k1
            float4 qv = *(const float4*)&hbuf[pb][kbase + kk + 2][0];
            a0 = fmaf(w[kk],   p.x, a0);  c0 = fmaf(w[kk],   p.y, c0);
            a1 = fmaf(w[kk+1], p.z, a1);  c1 = fmaf(w[kk+1], p.w, c1);
            a2 = fmaf(w[kk+2], qv.x, a2); c2 = fmaf(w[kk+2], qv.y, c2);
            a3 = fmaf(w[kk+3], qv.z, a3); c3 = fmaf(w[kk+3], qv.w, c3);
        }
        part_sm[0][tid] = (a0 + a1) + (a2 + a3);
        part_sm[1][tid] = (c0 + c1) + (c2 + c3);
        __syncthreads();

        // ---- assemble lin totals (threads 0..127 own row r) ----
        if (tid < 128) {
            lt_sm[0][r] = part_sm[0][r] + part_sm[0][128 + r] + pre0 + bias_r;
            lt_sm[1][r] = part_sm[1][r] + part_sm[1][128 + r] + pre1 + bias_r;
        }
        __syncthreads();

        // ---- gates: warp0 = batch0, warp1 = batch1 ----
        if (wrp < 2) {
            int bw = wrp;
            float iv = lt_sm[bw][lane];
            float fv = lt_sm[bw][32 + lane];
            float zv = lt_sm[bw][64 + lane];
            float ov = lt_sm[bw][96 + lane];
            float zg = tanhf(zv);
            float og = 1.f / (1.f + __expf(-ov));
            float mn = fmaxf(fv + m_s, iv);
            float ie = __expf(iv - mn);
            float fe = __expf(fv + m_s - mn);
            c_s = fe * c_s + ie * zg;
            n_s = fe * n_s + ie;
            m_s = mn;
            float hval = og * (c_s / n_s);
            h_loc[bw][lane] = hval;
            float s1 = hval, s2 = hval * hval;
#pragma unroll
            for (int o = 16; o; o >>= 1) {
                s1 += __shfl_xor_sync(0xffffffffu, s1, o);
                s2 += __shfl_xor_sync(0xffffffffu, s2, o);
            }
            if (lane == 0) { my_sums[2*bw] = s1; my_sums[2*bw + 1] = s2; }
        }
        __syncthreads();

        // ---- push h slice + partial sums to all 8 cluster CTAs ----
        {
            int peer = tid >> 5;                 // 0..7
            int sl   = tid & 31;
            float h0 = h_loc[0][sl], h1 = h_loc[1][sl];
            uint64_t pk;
            asm("mov.b64 %0, {%1,%2};" : "=l"(pk) : "f"(h0), "f"(h1));
            uint32_t laddr = smem_u32(&hbuf[nb][jj * 32 + sl][0]);
            uint32_t raddr;
            asm("mapa.shared::cluster.u32 %0, %1, %2;"
                : "=r"(raddr) : "r"(laddr), "r"(peer));
            asm volatile("st.shared::cluster.b64 [%0], %1;"
                         :: "r"(raddr), "l"(pk) : "memory");
            if (tid < 32) {
                int p2 = tid >> 2, item = tid & 3;
                uint32_t la = smem_u32(&sumbuf[nb][jj * 4 + item]);
                uint32_t ra;
                asm("mapa.shared::cluster.u32 %0, %1, %2;"
                    : "=r"(ra) : "r"(la), "r"(p2));
                asm volatile("st.shared::cluster.f32 [%0], %1;"
                             :: "r"(ra), "f"(my_sums[item]) : "memory");
            }
        }

        // ---- cluster barrier (release/acquire orders the remote stores) ----
        asm volatile("barrier.cluster.arrive.aligned;" ::: "memory");
        asm volatile("barrier.cluster.wait.aligned;" ::: "memory");

        // ---- groupnorm finalize + zn store (warps 0/1) ----
        if (wrp < 2) {
            int bw = wrp;
            float t1 = 0.f, t2 = 0.f;
#pragma unroll
            for (int p = 0; p < 8; p++) {
                t1 += sumbuf[nb][p * 4 + 2 * bw];
                t2 += sumbuf[nb][p * 4 + 2 * bw + 1];
            }
            float mean = t1 * (1.0f / HSZ);
            float var  = t2 * (1.0f / HSZ) - mean * mean;
            float rstd = rsqrtf(var + 1e-5f);
            float hval = h_loc[bw][lane];
            float znv  = (hval - mean) * rstd * gw + gb;
            int bcur = (bw == 0) ? b0 : b1;
            zn[((size_t)(bcur * TT + t)) * DD + h * HSZ + s_loc] = znv;
        }
        // hbuf[nb] fully written by peers (barrier passed); loop continues
    }
}

// ================= tf32 tensor-core GEMM ======================================
__device__ __forceinline__ uint32_t f2tf32(float f) {
    uint32_t r;
    asm("cvt.rna.tf32.f32 %0, %1;" : "=r"(r) : "f"(f));
    return r;
}

__device__ __forceinline__ void mma_tf32(float c[4], const uint32_t a[4],
                                         const uint32_t b[2]) {
    asm volatile(
        "mma.sync.aligned.m16n8k8.row.col.f32.tf32.tf32.f32 "
        "{%0,%1,%2,%3},{%4,%5,%6,%7},{%8,%9},{%0,%1,%2,%3};\n"
        : "+f"(c[0]), "+f"(c[1]), "+f"(c[2]), "+f"(c[3])
        : "r"(a[0]), "r"(a[1]), "r"(a[2]), "r"(a[3]), "r"(b[0]), "r"(b[1]));
}

__device__ __forceinline__ void cp16(uint32_t dst, const void* src, int srcsize) {
    asm volatile("cp.async.cg.shared.global [%0], [%1], 16, %2;\n"
                 :: "r"(dst), "l"(src), "r"(srcsize));
}

template <int MODE>
__global__ void __launch_bounds__(256) gemm_mma(
        const float* __restrict__ A, const float* __restrict__ W,
        float* __restrict__ C,
        int M, int N, int K, int lda, int ldw, int ldc,
        const float* __restrict__ bias, const float* __restrict__ resid)
{
    extern __shared__ float sm[];
    uint32_t sbase = (uint32_t)__cvta_generic_to_shared(sm);
    const float* Abuf[2] = { sm,            sm + BUFE };
    const float* Wbuf[2] = { sm + 2*BUFE,   sm + 3*BUFE };

    int tid  = threadIdx.x;
    int warp = tid >> 5, lane = tid & 31;
    int g = lane >> 2, tig = lane & 3;
    int wm = (warp >> 2) * 64;
    int wn = (warp & 3) * 32;
    int bm = blockIdx.x * 128;
    int bn = blockIdx.y * 128;

    float acc[4][4][4];
#pragma unroll
    for (int mt = 0; mt < 4; mt++)
#pragma unroll
        for (int nt = 0; nt < 4; nt++)
#pragma unroll
            for (int rr = 0; rr < 4; rr++) acc[mt][nt][rr] = 0.f;

    int KT = K >> 5;

    auto fill = [&](int kt, int buf) {
        int k0 = kt * 32;
        uint32_t sA = sbase + (uint32_t)(buf * BUFE) * 4u;
        uint32_t sW = sbase + (uint32_t)((2 + buf) * BUFE) * 4u;
#pragma unroll
        for (int i = 0; i < 4; i++) {
            int idx = tid + i * 256;
            int row = idx >> 3;
            int c4  = idx & 7;
            uint32_t soff = (uint32_t)(row * SMS + c4 * 4) * 4u;
            const float* srcA = A + (size_t)(bm + row) * lda + k0 + c4 * 4;
            cp16(sA + soff, srcA, 16);
            int wr = bn + row;
            const float* srcW = W + (size_t)(wr < N ? wr : 0) * ldw + k0 + c4 * 4;
            cp16(sW + soff, srcW, wr < N ? 16 : 0);
        }
        asm volatile("cp.async.commit_group;\n");
    };

    fill(0, 0);

    for (int kt = 0; kt < KT; kt++) {
        int buf = kt & 1;
        if (kt + 1 < KT) {
            fill(kt + 1, buf ^ 1);
            asm volatile("cp.async.wait_group 1;\n");
        } else {
            asm volatile("cp.async.wait_group 0;\n");
        }
        __syncthreads();

        const float* Ab = Abuf[buf];
        const float* Wb = Wbuf[buf];
#pragma unroll
        for (int ks = 0; ks < 4; ks++) {
            int k0 = ks * 8;
            uint32_t afr[4][4];
#pragma unroll
            for (int mt = 0; mt < 4; mt++) {
                const float* p = Ab + (wm + mt * 16 + g) * SMS + k0 + tig;
                afr[mt][0] = f2tf32(p[0]);
                afr[mt][1] = f2tf32(p[8 * SMS]);
                afr[mt][2] = f2tf32(p[4]);
                afr[mt][3] = f2tf32(p[8 * SMS + 4]);
            }
            uint32_t bfr[4][2];
#pragma unroll
            for (int nt = 0; nt < 4; nt++) {
                const float* p = Wb + (wn + nt * 8 + g) * SMS + k0 + tig;
                bfr[nt][0] = f2tf32(p[0]);
                bfr[nt][1] = f2tf32(p[4]);
            }
#pragma unroll
            for (int mt = 0; mt < 4; mt++)
#pragma unroll
                for (int nt = 0; nt < 4; nt++)
                    mma_tf32(acc[mt][nt], afr[mt], bfr[nt]);
        }
        __syncthreads();
    }

#pragma unroll
    for (int mt = 0; mt < 4; mt++) {
        int m0 = bm + wm + mt * 16 + g;
#pragma unroll
        for (int nt = 0; nt < 4; nt++) {
            int n0 = bn + wn + nt * 8 + 2 * tig;
            if (n0 < N) {
                float v0 = acc[mt][nt][0];
                float v1 = acc[mt][nt][1];
                float v2 = acc[mt][nt][2];
                float v3 = acc[mt][nt][3];
                if (MODE >= 1) {
                    float bz0 = bias[n0], bz1 = bias[n0 + 1];
                    v0 += bz0; v1 += bz1; v2 += bz0; v3 += bz1;
                }
                if (MODE == 2) {
                    v0 += resid[(size_t)m0 * ldc + n0];
                    v1 += resid[(size_t)m0 * ldc + n0 + 1];
                    v2 += resid[(size_t)(m0 + 8) * ldc + n0];
                    v3 += resid[(size_t)(m0 + 8) * ldc + n0 + 1];
                }
                C[(size_t)m0 * ldc + n0]           = v0;
                C[(size_t)m0 * ldc + n0 + 1]       = v1;
                C[(size_t)(m0 + 8) * ldc + n0]     = v2;
                C[(size_t)(m0 + 8) * ldc + n0 + 1] = v3;
            }
        }
    }
}

// ---------------- gelu(u1)*u2 -------------------------------------------------
__global__ void act_kernel(const float* __restrict__ up, float* __restrict__ act) {
    int idx = blockIdx.x * blockDim.x + threadIdx.x;
    if (idx >= BT * UPAD) return;
    int row = idx / UPAD, j = idx - row * UPAD;
    float v = 0.f;
    if (j < UU) {
        float u1 = up[(size_t)row * 2730 + j];
        float u2 = up[(size_t)row * 2730 + UU + j];
        float gelu = 0.5f * u1 * (1.f + tanhf(0.7978845608028654f *
                                              (u1 + 0.044715f * u1 * u1 * u1)));
        v = gelu * u2;
    }
    act[idx] = v;
}

// ---------------- launch ------------------------------------------------------
extern "C" void kernel_launch(void* const* d_in, const int* in_sizes, int n_in,
                              void* d_out, int out_size) {
    const float* x      = (const float*)d_in[0];
    const float* ln_w   = (const float*)d_in[1];
    const float* ln_b   = (const float*)d_in[2];
    const float* conv_w = (const float*)d_in[3];
    const float* conv_b = (const float*)d_in[4];
    const float* w_if   = (const float*)d_in[5];
    const float* w_zo   = (const float*)d_in[6];
    const float* w_hh   = (const float*)d_in[7];
    const float* bias   = (const float*)d_in[8];
    const float* gn_w   = (const float*)d_in[9];
    const float* gn_b   = (const float*)d_in[10];
    const float* up_w   = (const float*)d_in[11];
    const float* up_b   = (const float*)d_in[12];
    const float* down_w = (const float*)d_in[13];
    const float* down_b = (const float*)d_in[14];
    float* out = (float*)d_out;

    static float *p_xn = nullptr, *p_ifin, *p_lif, *p_lzo, *p_zn, *p_up, *p_act,
                 *p_dwpad;
    if (!p_xn) {
        cudaGetSymbolAddress((void**)&p_xn,    g_xn);
        cudaGetSymbolAddress((void**)&p_ifin,  g_ifin);
        cudaGetSymbolAddress((void**)&p_lif,   g_lin_if);
        cudaGetSymbolAddress((void**)&p_lzo,   g_lin_zo);
        cudaGetSymbolAddress((void**)&p_zn,    g_zn);
        cudaGetSymbolAddress((void**)&p_up,    g_up);
        cudaGetSymbolAddress((void**)&p_act,   g_act);
        cudaGetSymbolAddress((void**)&p_dwpad, g_dwpad);
        cudaFuncSetAttribute(gemm_mma<0>,
            cudaFuncAttributeMaxDynamicSharedMemorySize, GEMM_SMEM);
        cudaFuncSetAttribute(gemm_mma<1>,
            cudaFuncAttributeMaxDynamicSharedMemorySize, GEMM_SMEM);
        cudaFuncSetAttribute(gemm_mma<2>,
            cudaFuncAttributeMaxDynamicSharedMemorySize, GEMM_SMEM);
    }

    // Launch order keeps scan at position 6 (ncu -s 5 -c 1 profiles it).
    ln_kernel  <<<BT, 256>>>(x, ln_w, ln_b, p_xn);                                  // 1
    conv_kernel<<<(BT * DD + 255) / 256, 256>>>(p_xn, conv_w, conv_b, p_ifin);      // 2
    gemm_mma<0><<<dim3(BT / 128, 2048 / 128), 256, GEMM_SMEM>>>(                    // 3
        p_ifin, w_if, p_lif, BT, 2048, 1024, 1024, 1024, 2048, nullptr, nullptr);
    gemm_mma<0><<<dim3(BT / 128, 2048 / 128), 256, GEMM_SMEM>>>(                    // 4
        p_xn, w_zo, p_lzo, BT, 2048, 1024, 1024, 1024, 2048, nullptr, nullptr);
    pad_dw_kernel<<<(DD * UPAD + 255) / 256, 256>>>(down_w, p_dwpad);               // 5
    scan_kernel<<<128, 256>>>(p_lif, p_lzo, w_hh, bias, gn_w, gn_b, p_zn);          // 6 (profiled)
    gemm_mma<1><<<dim3(BT / 128, (2730 + 127) / 128), 256, GEMM_SMEM>>>(            // 7
        p_zn, up_w, p_up, BT, 2730, 1024, 1024, 1024, 2730, up_b, nullptr);
    act_kernel<<<(BT * UPAD + 255) / 256, 256>>>(p_up, p_act);                      // 8
    gemm_mma<2><<<dim3(BT / 128, 1024 / 128), 256, GEMM_SMEM>>>(                    // 9
        p_act, p_dwpad, out, BT, 1024, UPAD, UPAD, UPAD, 1024, down_b, x);
}